// round 2
// baseline (speedup 1.0000x reference)
#include <cuda_runtime.h>
#include <math.h>
#include <stdint.h>

// Problem dims
#define Bv   64
#define Sv   64
#define Tv   63      // S-1 decode steps == encoder positions
#define Hv   512
#define Dv   512
#define Vvoc 32000
#define NBL  128     // persistent LSTM blocks (must be <= #SMs, co-resident)

// ----------------------------------------------------------------------------
// Static device scratch (no allocations allowed)
// ----------------------------------------------------------------------------
__device__ float d_E[(size_t)Tv * Bv * Dv];           // embedded inputs (t,b,d)
__device__ float d_encproj[(size_t)Bv * Tv * Hv];     // enc @ We^T + b   (b,e,k)
__device__ float d_ptop[(size_t)Tv * Bv * Hv];        // top @ Wh^T       (t*B+b, k)
__device__ float d_cat[(size_t)Tv * Bv * 2 * Hv];     // [top | weighted] rows t*B+b
__device__ float d_hbuf[2][2][Bv * Hv];               // [layer][parity][b*H+h]
__device__ float d_cbuf[2][Bv * Hv];                  // [layer][b*H+h]
__device__ float d_scores[(size_t)Tv * Tv * Bv];      // (t,e,b)
__device__ float d_att[(size_t)Tv * Bv * Tv];         // (t,b,e)
__device__ float d_logits[(size_t)Tv * Bv * Vvoc];    // 516 MB
__device__ float d_nll[Tv * Bv];
__device__ float d_cnt[Tv * Bv];

__device__ unsigned int          g_bar_cnt;
__device__ volatile unsigned int g_bar_gen;

__device__ __forceinline__ float sigm(float x) { return 1.0f / (1.0f + expf(-x)); }

// Software grid barrier: valid because all NBL blocks are co-resident.
__device__ __forceinline__ void grid_barrier() {
    __syncthreads();
    if (threadIdx.x == 0) {
        __threadfence();
        unsigned int gen = g_bar_gen;
        unsigned int ticket = atomicInc(&g_bar_cnt, NBL - 1);
        if (ticket == NBL - 1) {
            g_bar_gen = gen + 1;
        } else {
            while (g_bar_gen == gen) { }
        }
        __threadfence();
    }
    __syncthreads();
}

// ----------------------------------------------------------------------------
// init: zero LSTM state (must happen every launch; d_out is repoisoned)
// ----------------------------------------------------------------------------
__global__ void init_kernel() {
    int i = blockIdx.x * blockDim.x + threadIdx.x;       // 256*512 = 131072 threads
    float* hb = &d_hbuf[0][0][0];
    float* cb = &d_cbuf[0][0];
    if (i < 2 * 2 * Bv * Hv) hb[i] = 0.0f;
    if (i < 2 * Bv * Hv)     cb[i] = 0.0f;
}

// ----------------------------------------------------------------------------
// embedding gather: E[t*B+b][:] = emb[X[b][t]]
// ----------------------------------------------------------------------------
__global__ void embed_kernel(const int* __restrict__ X, const float* __restrict__ emb) {
    int row = blockIdx.x;                 // t*64 + b
    int t = row >> 6, b = row & 63;
    int v = X[b * Sv + t];
    const float* src = emb + (size_t)v * Dv;
    float* dst = &d_E[(size_t)row * Dv];
    for (int k = threadIdx.x; k < Dv; k += 128) dst[k] = src[k];
}

// ----------------------------------------------------------------------------
// Generic NT GEMM: C[m,n] = sum_k A[m,k]*B[n,k] + bias[n]
// 128x128 block tile, BK=16, 8x8 per thread, 256 threads.
// ----------------------------------------------------------------------------
__global__ __launch_bounds__(256) void gemm_nt(
    const float* __restrict__ A, int lda,
    const float* __restrict__ Bm, int ldb,
    const float* __restrict__ bias,
    float* __restrict__ C, int ldc,
    int M, int N, int K)
{
    __shared__ float As[16][128];
    __shared__ float Bs[16][128];
    const int bm = blockIdx.y * 128, bn = blockIdx.x * 128;
    const int tid = threadIdx.x;
    const int tm = (tid >> 4) << 3;
    const int tn = (tid & 15) << 3;

    float acc[8][8];
#pragma unroll
    for (int i = 0; i < 8; i++)
#pragma unroll
        for (int j = 0; j < 8; j++) acc[i][j] = 0.0f;

    for (int k0 = 0; k0 < K; k0 += 16) {
#pragma unroll
        for (int i = 0; i < 2; i++) {
            int idx = tid + i * 256;           // 0..511 (float4 index)
            int r = idx >> 2;                  // 0..127
            int k4 = (idx & 3) << 2;           // 0,4,8,12
            float4 v = make_float4(0.f, 0.f, 0.f, 0.f);
            if (bm + r < M) v = *(const float4*)(A + (size_t)(bm + r) * lda + k0 + k4);
            As[k4 + 0][r] = v.x; As[k4 + 1][r] = v.y; As[k4 + 2][r] = v.z; As[k4 + 3][r] = v.w;
        }
#pragma unroll
        for (int i = 0; i < 2; i++) {
            int idx = tid + i * 256;
            int r = idx >> 2;
            int k4 = (idx & 3) << 2;
            float4 v = make_float4(0.f, 0.f, 0.f, 0.f);
            if (bn + r < N) v = *(const float4*)(Bm + (size_t)(bn + r) * ldb + k0 + k4);
            Bs[k4 + 0][r] = v.x; Bs[k4 + 1][r] = v.y; Bs[k4 + 2][r] = v.z; Bs[k4 + 3][r] = v.w;
        }
        __syncthreads();
#pragma unroll
        for (int kk = 0; kk < 16; kk++) {
            float a[8], b[8];
            *(float4*)&a[0] = *(const float4*)&As[kk][tm];
            *(float4*)&a[4] = *(const float4*)&As[kk][tm + 4];
            *(float4*)&b[0] = *(const float4*)&Bs[kk][tn];
            *(float4*)&b[4] = *(const float4*)&Bs[kk][tn + 4];
#pragma unroll
            for (int i = 0; i < 8; i++)
#pragma unroll
                for (int j = 0; j < 8; j++) acc[i][j] += a[i] * b[j];
        }
        __syncthreads();
    }

#pragma unroll
    for (int i = 0; i < 8; i++) {
        int m = bm + tm + i;
        if (m >= M) continue;
#pragma unroll
        for (int j = 0; j < 8; j += 4) {
            int n = bn + tn + j;
            if (n + 3 < N) {
                float4 v;
                float b0 = bias ? bias[n + 0] : 0.f;
                float b1 = bias ? bias[n + 1] : 0.f;
                float b2 = bias ? bias[n + 2] : 0.f;
                float b3 = bias ? bias[n + 3] : 0.f;
                v.x = acc[i][j + 0] + b0;
                v.y = acc[i][j + 1] + b1;
                v.z = acc[i][j + 2] + b2;
                v.w = acc[i][j + 3] + b3;
                *(float4*)(C + (size_t)m * ldc + n) = v;
            }
        }
    }
}

// ----------------------------------------------------------------------------
// Persistent LSTM over 63 steps, 2 layers. 128 blocks; block bid owns hidden
// units [4*bid, 4*bid+4) x all 4 gates (16 output columns) x all 64 batch rows.
// One grid barrier per step (between layer 0 and layer 1); h is double-buffered.
// ----------------------------------------------------------------------------
__global__ __launch_bounds__(256) void lstm_kernel(
    const float* __restrict__ Wih, const float* __restrict__ Whh,
    const float* __restrict__ bih, const float* __restrict__ bhh)
{
    const int bid = blockIdx.x, tid = threadIdx.x;
    const int tx = tid & 15, ty = tid >> 4;           // col 0..15, row-group 0..15
    const int gate = tx >> 2, iu = tx & 3;
    const int jcol = gate * 512 + bid * 4 + iu;       // this thread's output column

    __shared__ float As[64][68];
    __shared__ float Ws[16][68];
    __shared__ float gb[64][17];

    for (int t = 0; t < Tv; t++) {
        const int p = t & 1;
        for (int l = 0; l < 2; l++) {
            const float* xin = (l == 0) ? &d_E[(size_t)t * Bv * Dv] : d_hbuf[0][p ^ 1];
            const float* hp  = d_hbuf[l][p];
            const float* wih = Wih + (size_t)l * 2048 * 512;
            const float* whh = Whh + (size_t)l * 2048 * 512;

            float acc0 = 0.f, acc1 = 0.f, acc2 = 0.f, acc3 = 0.f;

            for (int kc = 0; kc < 16; kc++) {
                const int kb = kc * 64;
                const bool first = (kb < 512);
                const int koff = first ? kb : kb - 512;
                const float* abase = first ? xin : hp;
                const float* wbase = first ? wih : whh;
                // load A tile 64x64 (coalesced)
#pragma unroll
                for (int i = 0; i < 16; i++) {
                    int li = tid + 256 * i;
                    int b = li >> 6, kk = li & 63;
                    As[b][kk] = abase[b * 512 + koff + kk];
                }
                // load W tile 16x64
#pragma unroll
                for (int i = 0; i < 4; i++) {
                    int li = tid + 256 * i;
                    int c = li >> 6, kk = li & 63;
                    int j = ((c >> 2) * 512) + bid * 4 + (c & 3);
                    Ws[c][kk] = wbase[(size_t)j * 512 + koff + kk];
                }
                __syncthreads();
#pragma unroll
                for (int kk = 0; kk < 64; kk += 4) {
                    float4 w  = *(const float4*)&Ws[tx][kk];
                    float4 a0 = *(const float4*)&As[ty][kk];
                    float4 a1 = *(const float4*)&As[ty + 16][kk];
                    float4 a2 = *(const float4*)&As[ty + 32][kk];
                    float4 a3 = *(const float4*)&As[ty + 48][kk];
                    acc0 += a0.x * w.x + a0.y * w.y + a0.z * w.z + a0.w * w.w;
                    acc1 += a1.x * w.x + a1.y * w.y + a1.z * w.z + a1.w * w.w;
                    acc2 += a2.x * w.x + a2.y * w.y + a2.z * w.z + a2.w * w.w;
                    acc3 += a3.x * w.x + a3.y * w.y + a3.z * w.z + a3.w * w.w;
                }
                __syncthreads();
            }
            const float bsum = bih[l * 2048 + jcol] + bhh[l * 2048 + jcol];
            gb[ty     ][tx] = acc0 + bsum;
            gb[ty + 16][tx] = acc1 + bsum;
            gb[ty + 32][tx] = acc2 + bsum;
            gb[ty + 48][tx] = acc3 + bsum;
            __syncthreads();
            {
                int b = tid >> 2, i2 = tid & 3;
                float ig = gb[b][0 + i2];
                float fg = gb[b][4 + i2];
                float gg = gb[b][8 + i2];
                float og = gb[b][12 + i2];
                int h2 = bid * 4 + i2;
                float cprev = d_cbuf[l][b * 512 + h2];
                float cn = sigm(fg) * cprev + sigm(ig) * tanhf(gg);
                float hn = sigm(og) * tanhf(cn);
                d_cbuf[l][b * 512 + h2] = cn;
                d_hbuf[l][p ^ 1][b * 512 + h2] = hn;
                if (l == 1) d_cat[(size_t)(t * 64 + b) * 1024 + h2] = hn;
            }
            if (l == 0) grid_barrier();
            else        __syncthreads();
        }
    }
}

// ----------------------------------------------------------------------------
// scores[t,e,b] = sum_k tanh(ptop[t*B+b,k] + encproj[b,e,k]) * v_w[k]
// ----------------------------------------------------------------------------
__global__ void scores_kernel(const float* __restrict__ vw) {
    __shared__ float sP[512];
    __shared__ float sv[512];
    int tb = blockIdx.x;
    int t = tb >> 6, b = tb & 63;
    int tid = threadIdx.x;                    // 256
    for (int k = tid; k < 512; k += 256) { sP[k] = d_ptop[(size_t)tb * 512 + k]; sv[k] = vw[k]; }
    __syncthreads();
    int w = tid >> 5, lane = tid & 31;        // 8 warps
    for (int e = w; e < Tv; e += 8) {
        const float* ep = &d_encproj[((size_t)b * Tv + e) * 512];
        float s = 0.f;
        for (int k = lane; k < 512; k += 32) s += tanhf(sP[k] + ep[k]) * sv[k];
#pragma unroll
        for (int o = 16; o; o >>= 1) s += __shfl_xor_sync(0xffffffffu, s, o);
        if (lane == 0) d_scores[((size_t)t * Tv + e) * 64 + b] = s;
    }
}

// ----------------------------------------------------------------------------
// att: softmax over the BATCH axis per (t,e) (exactly as the reference does).
// ----------------------------------------------------------------------------
__global__ void att_kernel(const unsigned char* __restrict__ mask) {
    __shared__ float red[64];
    int te = blockIdx.x;
    int t = te / Tv, e = te - t * Tv;
    int tid = threadIdx.x;                    // 64 == B
    int mrow = (t + Tv - 1) % Tv;             // python (t-1) % 63
    float val = (mask[mrow * Tv + e] != 0) ? -1.0e9f : d_scores[(size_t)te * 64 + tid];
    red[tid] = val; __syncthreads();
    for (int s = 32; s; s >>= 1) { if (tid < s) red[tid] = fmaxf(red[tid], red[tid + s]); __syncthreads(); }
    float mx = red[0]; __syncthreads();
    float ev = expf(val - mx);
    red[tid] = ev; __syncthreads();
    for (int s = 32; s; s >>= 1) { if (tid < s) red[tid] += red[tid + s]; __syncthreads(); }
    d_att[((size_t)t * 64 + tid) * Tv + e] = ev / red[0];
}

// ----------------------------------------------------------------------------
// weighted[t*B+b][h] = sum_e att[t,b,e] * enc[b,e,h]  -> d_cat cols [512,1024)
// ----------------------------------------------------------------------------
__global__ void weighted_kernel(const float* __restrict__ enc) {
    __shared__ float sa[64];
    int tb = blockIdx.x;
    int b = tb & 63;
    int tid = threadIdx.x;                    // 512
    if (tid < Tv) sa[tid] = d_att[(size_t)tb * Tv + tid];
    __syncthreads();
    const float* eb = enc + (size_t)b * Tv * 512;
    float acc = 0.f;
    for (int e = 0; e < Tv; e++) acc += sa[e] * eb[e * 512 + tid];
    d_cat[(size_t)tb * 1024 + 512 + tid] = acc;
}

// ----------------------------------------------------------------------------
// per-row log-softmax NLL over V=32000
// ----------------------------------------------------------------------------
__global__ void nll_kernel(const int* __restrict__ X) {
    int r = blockIdx.x;
    int tid = threadIdx.x;                    // 256
    const float* row = d_logits + (size_t)r * Vvoc;
    __shared__ float red[256];
    float mx = -3.4e38f;
    for (int v = tid; v < Vvoc; v += 256) mx = fmaxf(mx, row[v]);
    red[tid] = mx; __syncthreads();
    for (int s = 128; s; s >>= 1) { if (tid < s) red[tid] = fmaxf(red[tid], red[tid + s]); __syncthreads(); }
    float M = red[0]; __syncthreads();
    float sm = 0.f;
    for (int v = tid; v < Vvoc; v += 256) sm += expf(row[v] - M);
    red[tid] = sm; __syncthreads();
    for (int s = 128; s; s >>= 1) { if (tid < s) red[tid] += red[tid + s]; __syncthreads(); }
    if (tid == 0) {
        int t = r >> 6, b = r & 63;
        int tgt = X[b * Sv + t + 1];
        float lp = row[tgt] - M - logf(red[0]);
        bool valid = (tgt != 0);
        d_nll[r] = valid ? -lp : 0.f;
        d_cnt[r] = valid ? 1.f : 0.f;
    }
}

// loss = mean_t( sum_b nll / sum_b valid )
__global__ void final_kernel(float* __restrict__ out) {
    __shared__ float red[64];
    int tid = threadIdx.x;                    // 64
    float lt = 0.f;
    if (tid < Tv) {
        float s = 0.f, c = 0.f;
        for (int b = 0; b < 64; b++) { s += d_nll[tid * 64 + b]; c += d_cnt[tid * 64 + b]; }
        lt = s / c;
    }
    red[tid] = lt; __syncthreads();
    for (int s = 32; s; s >>= 1) { if (tid < s) red[tid] += red[tid + s]; __syncthreads(); }
    if (tid == 0) out[0] = red[0] / (float)Tv;
}

// ----------------------------------------------------------------------------
extern "C" void kernel_launch(void* const* d_in, const int* in_sizes, int n_in,
                              void* d_out, int out_size)
{
    const int*   X    = (const int*)d_in[0];
    const float* enc  = (const float*)d_in[1];
    const unsigned char* mask = (const unsigned char*)d_in[2];
    const float* emb  = (const float*)d_in[3];
    const float* Wih  = (const float*)d_in[4];
    const float* Whh  = (const float*)d_in[5];
    const float* bih  = (const float*)d_in[6];
    const float* bhh  = (const float*)d_in[7];
    const float* aWh  = (const float*)d_in[8];
    const float* aWe  = (const float*)d_in[9];
    const float* ab   = (const float*)d_in[10];
    const float* vw   = (const float*)d_in[11];
    const float* fcW  = (const float*)d_in[12];
    const float* fcb  = (const float*)d_in[13];
    float* out = (float*)d_out;

    float *p_encproj, *p_ptop, *p_cat, *p_logits;
    cudaGetSymbolAddress((void**)&p_encproj, d_encproj);
    cudaGetSymbolAddress((void**)&p_ptop,    d_ptop);
    cudaGetSymbolAddress((void**)&p_cat,     d_cat);
    cudaGetSymbolAddress((void**)&p_logits,  d_logits);

    init_kernel<<<256, 512>>>();
    embed_kernel<<<Tv * Bv, 128>>>(X, emb);
    // enc_proj = enc @ We^T + b : M=4032, N=512, K=512
    gemm_nt<<<dim3(4, 32), 256>>>(enc, Hv, aWe, Hv, ab, p_encproj, Hv, Tv * Bv, Hv, Hv);
    lstm_kernel<<<NBL, 256>>>(Wih, Whh, bih, bhh);
    // ptop = top @ Wh^T : A = d_cat (lda=1024, first 512 cols), no bias
    gemm_nt<<<dim3(4, 32), 256>>>(p_cat, 2 * Hv, aWh, Hv, nullptr, p_ptop, Hv, Tv * Bv, Hv, Hv);
    scores_kernel<<<Tv * Bv, 256>>>(vw);
    att_kernel<<<Tv * Tv, 64>>>(mask);
    weighted_kernel<<<Tv * Bv, 512>>>(enc);
    // logits = cat @ fcW^T + fcb : M=4032, N=32000, K=1024
    gemm_nt<<<dim3(Vvoc / 128, 32), 256>>>(p_cat, 2 * Hv, fcW, 2 * Hv, fcb, p_logits, Vvoc, Tv * Bv, Vvoc, 2 * Hv);
    nll_kernel<<<Tv * Bv, 256>>>(X);
    final_kernel<<<1, 64>>>(out);
}

// round 4
// speedup vs baseline: 2.3509x; 2.3509x over previous
#include <cuda_runtime.h>
#include <cuda_bf16.h>
#include <math.h>
#include <stdint.h>

// Problem dims
#define Bv   64
#define Sv   64
#define Tv   63
#define Hv   512
#define Dv   512
#define Vvoc 32000
#define NBL  128

// Tensor-core GEMM tiling (mma.sync path, no 'a'-gated features)
#define GM   128
#define GN   128
#define GKC  64             // K chunk (bf16) = 128 bytes/row
#define NKC  16             // 1024 / 64
#define MPAD 4096

// ----------------------------------------------------------------------------
// Static device scratch
// ----------------------------------------------------------------------------
__device__ float d_E[(size_t)Tv * Bv * Dv];
__device__ float d_encproj[(size_t)Bv * Tv * Hv];
__device__ float d_ptop[(size_t)Tv * Bv * Hv];
__device__ float d_cat[(size_t)Tv * Bv * 2 * Hv];
__device__ float d_hbuf[2][2][Bv * Hv];
__device__ float d_cbuf[2][Bv * Hv];
__device__ float d_scores[(size_t)Tv * Tv * Bv];
__device__ float d_att[(size_t)Tv * Bv * Tv];
__device__ float d_logits[(size_t)Tv * Bv * Vvoc];
__device__ float d_nll[Tv * Bv];
__device__ float d_cnt[Tv * Bv];
__device__ __nv_bfloat16 d_catb[(size_t)MPAD * 1024];
__device__ __nv_bfloat16 d_fcWb[(size_t)Vvoc * 1024];

__device__ unsigned int          g_bar_cnt;
__device__ volatile unsigned int g_bar_gen;

__device__ __forceinline__ float sigm(float x) { return 1.0f / (1.0f + expf(-x)); }

__device__ __forceinline__ void grid_barrier() {
    __syncthreads();
    if (threadIdx.x == 0) {
        __threadfence();
        unsigned int gen = g_bar_gen;
        unsigned int ticket = atomicInc(&g_bar_cnt, NBL - 1);
        if (ticket == NBL - 1) {
            g_bar_gen = gen + 1;
        } else {
            while (g_bar_gen == gen) { }
        }
        __threadfence();
    }
    __syncthreads();
}

// ----------------------------------------------------------------------------
// PTX helpers (all sm_80/90-baseline; nothing 'a'-gated)
// ----------------------------------------------------------------------------
__device__ __forceinline__ uint32_t smem_u32(const void* p) {
    uint32_t a;
    asm("{ .reg .u64 t; cvta.to.shared.u64 t, %1; cvt.u32.u64 %0, t; }" : "=r"(a) : "l"(p));
    return a;
}
__device__ __forceinline__ void cp_async16(uint32_t dst, const void* src) {
    asm volatile("cp.async.cg.shared.global [%0], [%1], 16;" :: "r"(dst), "l"(src) : "memory");
}
__device__ __forceinline__ void cp_commit() {
    asm volatile("cp.async.commit_group;" ::: "memory");
}
__device__ __forceinline__ uint32_t sw128(uint32_t off) { return off ^ ((off >> 3) & 0x70); }

__device__ __forceinline__ void ldmx4(uint32_t* r, uint32_t addr) {
    asm volatile("ldmatrix.sync.aligned.m8n8.x4.shared.b16 {%0,%1,%2,%3}, [%4];"
                 : "=r"(r[0]), "=r"(r[1]), "=r"(r[2]), "=r"(r[3]) : "r"(addr));
}
__device__ __forceinline__ void mma_bf16(float* c, const uint32_t* a, uint32_t b0, uint32_t b1) {
    asm volatile("mma.sync.aligned.m16n8k16.row.col.f32.bf16.bf16.f32 "
                 "{%0,%1,%2,%3}, {%4,%5,%6,%7}, {%8,%9}, {%0,%1,%2,%3};"
                 : "+f"(c[0]), "+f"(c[1]), "+f"(c[2]), "+f"(c[3])
                 : "r"(a[0]), "r"(a[1]), "r"(a[2]), "r"(a[3]), "r"(b0), "r"(b1));
}

// ----------------------------------------------------------------------------
__global__ void init_kernel() {
    int i = blockIdx.x * blockDim.x + threadIdx.x;
    float* hb = &d_hbuf[0][0][0];
    float* cb = &d_cbuf[0][0];
    if (i < 2 * 2 * Bv * Hv) hb[i] = 0.0f;
    if (i < 2 * Bv * Hv)     cb[i] = 0.0f;
}

__global__ void embed_kernel(const int* __restrict__ X, const float* __restrict__ emb) {
    int row = blockIdx.x;
    int t = row >> 6, b = row & 63;
    int v = X[b * Sv + t];
    const float* src = emb + (size_t)v * Dv;
    float* dst = &d_E[(size_t)row * Dv];
    for (int k = threadIdx.x; k < Dv; k += 128) dst[k] = src[k];
}

// fp32 GEMM kept for the two small H x H products
__global__ __launch_bounds__(256) void gemm_nt(
    const float* __restrict__ A, int lda,
    const float* __restrict__ Bm, int ldb,
    const float* __restrict__ bias,
    float* __restrict__ C, int ldc,
    int M, int N, int K)
{
    __shared__ float As[16][128];
    __shared__ float Bs[16][128];
    const int bm = blockIdx.y * 128, bn = blockIdx.x * 128;
    const int tid = threadIdx.x;
    const int tm = (tid >> 4) << 3;
    const int tn = (tid & 15) << 3;

    float acc[8][8];
#pragma unroll
    for (int i = 0; i < 8; i++)
#pragma unroll
        for (int j = 0; j < 8; j++) acc[i][j] = 0.0f;

    for (int k0 = 0; k0 < K; k0 += 16) {
#pragma unroll
        for (int i = 0; i < 2; i++) {
            int idx = tid + i * 256;
            int r = idx >> 2;
            int k4 = (idx & 3) << 2;
            float4 v = make_float4(0.f, 0.f, 0.f, 0.f);
            if (bm + r < M) v = *(const float4*)(A + (size_t)(bm + r) * lda + k0 + k4);
            As[k4 + 0][r] = v.x; As[k4 + 1][r] = v.y; As[k4 + 2][r] = v.z; As[k4 + 3][r] = v.w;
        }
#pragma unroll
        for (int i = 0; i < 2; i++) {
            int idx = tid + i * 256;
            int r = idx >> 2;
            int k4 = (idx & 3) << 2;
            float4 v = make_float4(0.f, 0.f, 0.f, 0.f);
            if (bn + r < N) v = *(const float4*)(Bm + (size_t)(bn + r) * ldb + k0 + k4);
            Bs[k4 + 0][r] = v.x; Bs[k4 + 1][r] = v.y; Bs[k4 + 2][r] = v.z; Bs[k4 + 3][r] = v.w;
        }
        __syncthreads();
#pragma unroll
        for (int kk = 0; kk < 16; kk++) {
            float a[8], b[8];
            *(float4*)&a[0] = *(const float4*)&As[kk][tm];
            *(float4*)&a[4] = *(const float4*)&As[kk][tm + 4];
            *(float4*)&b[0] = *(const float4*)&Bs[kk][tn];
            *(float4*)&b[4] = *(const float4*)&Bs[kk][tn + 4];
#pragma unroll
            for (int i = 0; i < 8; i++)
#pragma unroll
                for (int j = 0; j < 8; j++) acc[i][j] += a[i] * b[j];
        }
        __syncthreads();
    }

#pragma unroll
    for (int i = 0; i < 8; i++) {
        int m = bm + tm + i;
        if (m >= M) continue;
#pragma unroll
        for (int j = 0; j < 8; j += 4) {
            int n = bn + tn + j;
            if (n + 3 < N) {
                float4 v;
                float b0 = bias ? bias[n + 0] : 0.f;
                float b1 = bias ? bias[n + 1] : 0.f;
                float b2 = bias ? bias[n + 2] : 0.f;
                float b3 = bias ? bias[n + 3] : 0.f;
                v.x = acc[i][j + 0] + b0;
                v.y = acc[i][j + 1] + b1;
                v.z = acc[i][j + 2] + b2;
                v.w = acc[i][j + 3] + b3;
                *(float4*)(C + (size_t)m * ldc + n) = v;
            }
        }
    }
}

// ----------------------------------------------------------------------------
// Persistent 2-layer LSTM (unchanged)
// ----------------------------------------------------------------------------
__global__ __launch_bounds__(256) void lstm_kernel(
    const float* __restrict__ Wih, const float* __restrict__ Whh,
    const float* __restrict__ bih, const float* __restrict__ bhh)
{
    const int bid = blockIdx.x, tid = threadIdx.x;
    const int tx = tid & 15, ty = tid >> 4;
    const int gate = tx >> 2, iu = tx & 3;
    const int jcol = gate * 512 + bid * 4 + iu;

    __shared__ float As[64][68];
    __shared__ float Ws[16][68];
    __shared__ float gb[64][17];

    for (int t = 0; t < Tv; t++) {
        const int p = t & 1;
        for (int l = 0; l < 2; l++) {
            const float* xin = (l == 0) ? &d_E[(size_t)t * Bv * Dv] : d_hbuf[0][p ^ 1];
            const float* hp  = d_hbuf[l][p];
            const float* wih = Wih + (size_t)l * 2048 * 512;
            const float* whh = Whh + (size_t)l * 2048 * 512;

            float acc0 = 0.f, acc1 = 0.f, acc2 = 0.f, acc3 = 0.f;

            for (int kc = 0; kc < 16; kc++) {
                const int kb = kc * 64;
                const bool first = (kb < 512);
                const int koff = first ? kb : kb - 512;
                const float* abase = first ? xin : hp;
                const float* wbase = first ? wih : whh;
#pragma unroll
                for (int i = 0; i < 16; i++) {
                    int li = tid + 256 * i;
                    int b = li >> 6, kk = li & 63;
                    As[b][kk] = abase[b * 512 + koff + kk];
                }
#pragma unroll
                for (int i = 0; i < 4; i++) {
                    int li = tid + 256 * i;
                    int c = li >> 6, kk = li & 63;
                    int j = ((c >> 2) * 512) + bid * 4 + (c & 3);
                    Ws[c][kk] = wbase[(size_t)j * 512 + koff + kk];
                }
                __syncthreads();
#pragma unroll
                for (int kk = 0; kk < 64; kk += 4) {
                    float4 w  = *(const float4*)&Ws[tx][kk];
                    float4 a0 = *(const float4*)&As[ty][kk];
                    float4 a1 = *(const float4*)&As[ty + 16][kk];
                    float4 a2 = *(const float4*)&As[ty + 32][kk];
                    float4 a3 = *(const float4*)&As[ty + 48][kk];
                    acc0 += a0.x * w.x + a0.y * w.y + a0.z * w.z + a0.w * w.w;
                    acc1 += a1.x * w.x + a1.y * w.y + a1.z * w.z + a1.w * w.w;
                    acc2 += a2.x * w.x + a2.y * w.y + a2.z * w.z + a2.w * w.w;
                    acc3 += a3.x * w.x + a3.y * w.y + a3.z * w.z + a3.w * w.w;
                }
                __syncthreads();
            }
            const float bsum = bih[l * 2048 + jcol] + bhh[l * 2048 + jcol];
            gb[ty     ][tx] = acc0 + bsum;
            gb[ty + 16][tx] = acc1 + bsum;
            gb[ty + 32][tx] = acc2 + bsum;
            gb[ty + 48][tx] = acc3 + bsum;
            __syncthreads();
            {
                int b = tid >> 2, i2 = tid & 3;
                float ig = gb[b][0 + i2];
                float fg = gb[b][4 + i2];
                float gg = gb[b][8 + i2];
                float og = gb[b][12 + i2];
                int h2 = bid * 4 + i2;
                float cprev = d_cbuf[l][b * 512 + h2];
                float cn = sigm(fg) * cprev + sigm(ig) * tanhf(gg);
                float hn = sigm(og) * tanhf(cn);
                d_cbuf[l][b * 512 + h2] = cn;
                d_hbuf[l][p ^ 1][b * 512 + h2] = hn;
                if (l == 1) d_cat[(size_t)(t * 64 + b) * 1024 + h2] = hn;
            }
            if (l == 0) grid_barrier();
            else        __syncthreads();
        }
    }
}

// ----------------------------------------------------------------------------
__global__ void scores_kernel(const float* __restrict__ vw) {
    __shared__ float sP[512];
    __shared__ float sv[512];
    int tb = blockIdx.x;
    int t = tb >> 6, b = tb & 63;
    int tid = threadIdx.x;
    for (int k = tid; k < 512; k += 256) { sP[k] = d_ptop[(size_t)tb * 512 + k]; sv[k] = vw[k]; }
    __syncthreads();
    int w = tid >> 5, lane = tid & 31;
    for (int e = w; e < Tv; e += 8) {
        const float* ep = &d_encproj[((size_t)b * Tv + e) * 512];
        float s = 0.f;
        for (int k = lane; k < 512; k += 32) s += tanhf(sP[k] + ep[k]) * sv[k];
#pragma unroll
        for (int o = 16; o; o >>= 1) s += __shfl_xor_sync(0xffffffffu, s, o);
        if (lane == 0) d_scores[((size_t)t * Tv + e) * 64 + b] = s;
    }
}

__global__ void att_kernel(const unsigned char* __restrict__ mask) {
    __shared__ float red[64];
    int te = blockIdx.x;
    int t = te / Tv, e = te - t * Tv;
    int tid = threadIdx.x;
    int mrow = (t + Tv - 1) % Tv;
    float val = (mask[mrow * Tv + e] != 0) ? -1.0e9f : d_scores[(size_t)te * 64 + tid];
    red[tid] = val; __syncthreads();
    for (int s = 32; s; s >>= 1) { if (tid < s) red[tid] = fmaxf(red[tid], red[tid + s]); __syncthreads(); }
    float mx = red[0]; __syncthreads();
    float ev = expf(val - mx);
    red[tid] = ev; __syncthreads();
    for (int s = 32; s; s >>= 1) { if (tid < s) red[tid] += red[tid + s]; __syncthreads(); }
    d_att[((size_t)t * 64 + tid) * Tv + e] = ev / red[0];
}

__global__ void weighted_kernel(const float* __restrict__ enc) {
    __shared__ float sa[64];
    int tb = blockIdx.x;
    int b = tb & 63;
    int tid = threadIdx.x;
    if (tid < Tv) sa[tid] = d_att[(size_t)tb * Tv + tid];
    __syncthreads();
    const float* eb = enc + (size_t)b * Tv * 512;
    float acc = 0.f;
    for (int e = 0; e < Tv; e++) acc += sa[e] * eb[e * 512 + tid];
    d_cat[(size_t)tb * 1024 + 512 + tid] = acc;
}

// ----------------------------------------------------------------------------
// bf16 conversions
// ----------------------------------------------------------------------------
__global__ void conv_cat_kernel() {
    size_t i = (size_t)blockIdx.x * blockDim.x + threadIdx.x;
    size_t row = i >> 9;
    float2 v = make_float2(0.f, 0.f);
    if (row < (size_t)Tv * Bv) v = *((const float2*)d_cat + i);
    *((__nv_bfloat162*)d_catb + i) = __floats2bfloat162_rn(v.x, v.y);
}
__global__ void conv_w_kernel(const float* __restrict__ fcW) {
    size_t i = (size_t)blockIdx.x * blockDim.x + threadIdx.x;
    float2 v = *((const float2*)fcW + i);
    *((__nv_bfloat162*)d_fcWb + i) = __floats2bfloat162_rn(v.x, v.y);
}

// ----------------------------------------------------------------------------
// HMMA bf16 GEMM (mma.sync): logits[m,n] = catb[m,:].fcWb[n,:] + fcb[n]
// 128x128 CTA tile, BK=64, double-buffered cp.async, SW128 swizzle.
// 8 warps in 4(M) x 2(N); warp tile 32x64.
// grid (32 m-tiles, 250 n-tiles): x-fastest keeps one B tile shared in L2.
// ----------------------------------------------------------------------------
#define SA_OFF  0
#define SB_OFF  32768
#define SM_DYN  65536

__global__ __launch_bounds__(256, 2) void gemm_hmma(const float* __restrict__ fcb)
{
    extern __shared__ char smem[];
    const uint32_t sbase = smem_u32(smem);
    const int tid = threadIdx.x, wid = tid >> 5, lane = tid & 31;
    const int wm = wid & 3, wn = wid >> 2;
    const int m0 = blockIdx.x * GM;
    const int n0 = blockIdx.y * GN;

    float c[2][8][4];
#pragma unroll
    for (int mt = 0; mt < 2; mt++)
#pragma unroll
        for (int nt = 0; nt < 8; nt++)
#pragma unroll
            for (int k = 0; k < 4; k++) c[mt][nt][k] = 0.0f;

    // per-thread cp.async coordinates (4 segments of 16B for A, 4 for B)
    // tile = 128 rows x 128 bytes; i = row*8 + seg
    const __nv_bfloat16* Ag = d_catb + (size_t)m0 * 1024;
    const __nv_bfloat16* Bg = d_fcWb + (size_t)n0 * 1024;

    // prologue: load chunk 0 into buffer 0
#pragma unroll
    for (int p = 0; p < 4; p++) {
        int i = tid + p * 256;
        int row = i >> 3, seg = i & 7;
        uint32_t off = sw128((uint32_t)(row * 128 + seg * 16));
        cp_async16(sbase + SA_OFF + off, (const char*)(Ag + (size_t)row * 1024) + seg * 16);
    }
#pragma unroll
    for (int p = 0; p < 4; p++) {
        int i = tid + p * 256;
        int row = i >> 3, seg = i & 7;
        uint32_t off = sw128((uint32_t)(row * 128 + seg * 16));
        cp_async16(sbase + SB_OFF + off, (const char*)(Bg + (size_t)row * 1024) + seg * 16);
    }
    cp_commit();

    for (int it = 0; it < NKC; it++) {
        if (it + 1 < NKC) {
            const int k0 = (it + 1) * GKC;          // bf16 elements
            const uint32_t bufo = ((it + 1) & 1) * 16384;
#pragma unroll
            for (int p = 0; p < 4; p++) {
                int i = tid + p * 256;
                int row = i >> 3, seg = i & 7;
                uint32_t off = sw128((uint32_t)(row * 128 + seg * 16));
                cp_async16(sbase + SA_OFF + bufo + off,
                           (const char*)(Ag + (size_t)row * 1024 + k0) + seg * 16);
            }
#pragma unroll
            for (int p = 0; p < 4; p++) {
                int i = tid + p * 256;
                int row = i >> 3, seg = i & 7;
                uint32_t off = sw128((uint32_t)(row * 128 + seg * 16));
                cp_async16(sbase + SB_OFF + bufo + off,
                           (const char*)(Bg + (size_t)row * 1024 + k0) + seg * 16);
            }
            cp_commit();
            asm volatile("cp.async.wait_group 1;" ::: "memory");
        } else {
            asm volatile("cp.async.wait_group 0;" ::: "memory");
        }
        __syncthreads();

        const uint32_t abase = sbase + SA_OFF + (it & 1) * 16384;
        const uint32_t bbase = sbase + SB_OFF + (it & 1) * 16384;
#pragma unroll
        for (int ks = 0; ks < 4; ks++) {
            uint32_t af[2][4];
#pragma unroll
            for (int mt = 0; mt < 2; mt++) {
                int arow = wm * 32 + mt * 16 + (lane & 15);
                int acol = ks * 32 + ((lane >> 4) << 4);
                ldmx4(af[mt], abase + sw128((uint32_t)(arow * 128 + acol)));
            }
            uint32_t bf[4][4];
#pragma unroll
            for (int j = 0; j < 4; j++) {
                int brow = wn * 64 + j * 16 + ((lane >> 4) << 3) + (lane & 7);
                int bcol = ks * 32 + (((lane >> 3) & 1) << 4);
                ldmx4(bf[j], bbase + sw128((uint32_t)(brow * 128 + bcol)));
            }
#pragma unroll
            for (int mt = 0; mt < 2; mt++)
#pragma unroll
                for (int nt = 0; nt < 8; nt++)
                    mma_bf16(c[mt][nt], af[mt], bf[nt >> 1][(nt & 1) * 2], bf[nt >> 1][(nt & 1) * 2 + 1]);
        }
        __syncthreads();
    }

    // epilogue: direct stores (row-major; float2 per fragment pair) + bias
#pragma unroll
    for (int mt = 0; mt < 2; mt++) {
        int r0 = m0 + wm * 32 + mt * 16 + (lane >> 2);
        int r1 = r0 + 8;
#pragma unroll
        for (int nt = 0; nt < 8; nt++) {
            int col = n0 + wn * 64 + nt * 8 + (lane & 3) * 2;
            float b0 = fcb[col], b1 = fcb[col + 1];
            if (r0 < Tv * Bv) {
                float2 v = make_float2(c[mt][nt][0] + b0, c[mt][nt][1] + b1);
                *(float2*)(d_logits + (size_t)r0 * Vvoc + col) = v;
            }
            if (r1 < Tv * Bv) {
                float2 v = make_float2(c[mt][nt][2] + b0, c[mt][nt][3] + b1);
                *(float2*)(d_logits + (size_t)r1 * Vvoc + col) = v;
            }
        }
    }
}

// ----------------------------------------------------------------------------
__global__ void nll_kernel(const int* __restrict__ X) {
    int r = blockIdx.x;
    int tid = threadIdx.x;
    const float* row = d_logits + (size_t)r * Vvoc;
    __shared__ float red[256];
    float mx = -3.4e38f;
    for (int v = tid; v < Vvoc; v += 256) mx = fmaxf(mx, row[v]);
    red[tid] = mx; __syncthreads();
    for (int s = 128; s; s >>= 1) { if (tid < s) red[tid] = fmaxf(red[tid], red[tid + s]); __syncthreads(); }
    float M = red[0]; __syncthreads();
    float sm = 0.f;
    for (int v = tid; v < Vvoc; v += 256) sm += expf(row[v] - M);
    red[tid] = sm; __syncthreads();
    for (int s = 128; s; s >>= 1) { if (tid < s) red[tid] += red[tid + s]; __syncthreads(); }
    if (tid == 0) {
        int t = r >> 6, b = r & 63;
        int tgt = X[b * Sv + t + 1];
        float lp = row[tgt] - M - logf(red[0]);
        bool valid = (tgt != 0);
        d_nll[r] = valid ? -lp : 0.f;
        d_cnt[r] = valid ? 1.f : 0.f;
    }
}

__global__ void final_kernel(float* __restrict__ out) {
    __shared__ float red[64];
    int tid = threadIdx.x;
    float lt = 0.f;
    if (tid < Tv) {
        float s = 0.f, c = 0.f;
        for (int b = 0; b < 64; b++) { s += d_nll[tid * 64 + b]; c += d_cnt[tid * 64 + b]; }
        lt = s / c;
    }
    red[tid] = lt; __syncthreads();
    for (int s = 32; s; s >>= 1) { if (tid < s) red[tid] += red[tid + s]; __syncthreads(); }
    if (tid == 0) out[0] = red[0] / (float)Tv;
}

// ----------------------------------------------------------------------------
extern "C" void kernel_launch(void* const* d_in, const int* in_sizes, int n_in,
                              void* d_out, int out_size)
{
    const int*   X    = (const int*)d_in[0];
    const float* enc  = (const float*)d_in[1];
    const unsigned char* mask = (const unsigned char*)d_in[2];
    const float* emb  = (const float*)d_in[3];
    const float* Wih  = (const float*)d_in[4];
    const float* Whh  = (const float*)d_in[5];
    const float* bih  = (const float*)d_in[6];
    const float* bhh  = (const float*)d_in[7];
    const float* aWh  = (const float*)d_in[8];
    const float* aWe  = (const float*)d_in[9];
    const float* ab   = (const float*)d_in[10];
    const float* vw   = (const float*)d_in[11];
    const float* fcW  = (const float*)d_in[12];
    const float* fcb  = (const float*)d_in[13];
    float* out = (float*)d_out;

    float *p_encproj, *p_ptop, *p_cat;
    cudaGetSymbolAddress((void**)&p_encproj, d_encproj);
    cudaGetSymbolAddress((void**)&p_ptop,    d_ptop);
    cudaGetSymbolAddress((void**)&p_cat,     d_cat);

    cudaFuncSetAttribute(gemm_hmma, cudaFuncAttributeMaxDynamicSharedMemorySize, SM_DYN);

    init_kernel<<<256, 512>>>();
    embed_kernel<<<Tv * Bv, 128>>>(X, emb);
    gemm_nt<<<dim3(4, 32), 256>>>(enc, Hv, aWe, Hv, ab, p_encproj, Hv, Tv * Bv, Hv, Hv);
    lstm_kernel<<<NBL, 256>>>(Wih, Whh, bih, bhh);
    gemm_nt<<<dim3(4, 32), 256>>>(p_cat, 2 * Hv, aWh, Hv, nullptr, p_ptop, Hv, Tv * Bv, Hv, Hv);
    scores_kernel<<<Tv * Bv, 256>>>(vw);
    att_kernel<<<Tv * Tv, 64>>>(mask);
    weighted_kernel<<<Tv * Bv, 512>>>(enc);
    conv_w_kernel<<<(Vvoc * 1024 / 2) / 256, 256>>>(fcW);
    conv_cat_kernel<<<(MPAD * 1024 / 2) / 256, 256>>>();
    gemm_hmma<<<dim3(MPAD / GM, Vvoc / GN), 256, SM_DYN>>>(fcb);
    nll_kernel<<<Tv * Bv, 256>>>(X);
    final_kernel<<<1, 64>>>(out);
}

// round 5
// speedup vs baseline: 4.7704x; 2.0292x over previous
#include <cuda_runtime.h>
#include <cuda_bf16.h>
#include <math.h>
#include <stdint.h>

// Problem dims
#define Bv   64
#define Sv   64
#define Tv   63
#define Hv   512
#define Dv   512
#define Vvoc 32000
#define NBL  128

// Vocab GEMM tiling (mma.sync path)
#define GM   128
#define GN   128
#define GKC  64
#define NKC  16
#define MPAD 4096
#define NTILES (Vvoc / GN)     // 250

// ----------------------------------------------------------------------------
// Static device scratch
// ----------------------------------------------------------------------------
__device__ __nv_bfloat16 d_Eb[(size_t)Tv * Bv * Dv];        // embedded inputs bf16
__device__ float d_encproj[(size_t)Bv * Tv * Hv];
__device__ float d_ptop[(size_t)Tv * Bv * Hv];
__device__ float d_cat[(size_t)Tv * Bv * 2 * Hv];
__device__ __nv_bfloat16 d_hb[2][2][Bv * Hv];               // [layer][parity] bf16 h
__device__ float d_cbuf[2][Bv * Hv];
__device__ float d_scores[(size_t)Tv * Tv * Bv];
__device__ float d_att[(size_t)Tv * Bv * Tv];
__device__ float d_nll[Tv * Bv];
__device__ float d_cnt[Tv * Bv];
__device__ float d_ltgt[Tv * Bv];
__device__ float d_psum[(size_t)MPAD * 256];                // [row][ntile] partial sum-exp
__device__ __nv_bfloat16 d_catb[(size_t)MPAD * 1024];
__device__ __nv_bfloat16 d_fcWb[(size_t)Vvoc * 1024];
__device__ __nv_bfloat16 d_Wc[2][2048][1024];               // combined [Wih|Whh] bf16

__device__ unsigned int          g_bar_cnt;
__device__ volatile unsigned int g_bar_gen;

__device__ __forceinline__ float sigm(float x) { return 1.0f / (1.0f + expf(-x)); }

__device__ __forceinline__ void grid_barrier() {
    __syncthreads();
    if (threadIdx.x == 0) {
        __threadfence();
        unsigned int gen = g_bar_gen;
        unsigned int ticket = atomicInc(&g_bar_cnt, NBL - 1);
        if (ticket == NBL - 1) {
            g_bar_gen = gen + 1;
        } else {
            while (g_bar_gen == gen) { }
        }
        __threadfence();
    }
    __syncthreads();
}

// ----------------------------------------------------------------------------
// PTX helpers
// ----------------------------------------------------------------------------
__device__ __forceinline__ uint32_t smem_u32(const void* p) {
    uint32_t a;
    asm("{ .reg .u64 t; cvta.to.shared.u64 t, %1; cvt.u32.u64 %0, t; }" : "=r"(a) : "l"(p));
    return a;
}
__device__ __forceinline__ void cp_async16(uint32_t dst, const void* src) {
    asm volatile("cp.async.cg.shared.global [%0], [%1], 16;" :: "r"(dst), "l"(src) : "memory");
}
__device__ __forceinline__ void cp_commit() {
    asm volatile("cp.async.commit_group;" ::: "memory");
}
__device__ __forceinline__ uint32_t sw128(uint32_t off) { return off ^ ((off >> 3) & 0x70); }

__device__ __forceinline__ void ldmx4(uint32_t* r, uint32_t addr) {
    asm volatile("ldmatrix.sync.aligned.m8n8.x4.shared.b16 {%0,%1,%2,%3}, [%4];"
                 : "=r"(r[0]), "=r"(r[1]), "=r"(r[2]), "=r"(r[3]) : "r"(addr));
}
__device__ __forceinline__ void mma_bf16(float* c, const uint32_t* a, uint32_t b0, uint32_t b1) {
    asm volatile("mma.sync.aligned.m16n8k16.row.col.f32.bf16.bf16.f32 "
                 "{%0,%1,%2,%3}, {%4,%5,%6,%7}, {%8,%9}, {%0,%1,%2,%3};"
                 : "+f"(c[0]), "+f"(c[1]), "+f"(c[2]), "+f"(c[3])
                 : "r"(a[0]), "r"(a[1]), "r"(a[2]), "r"(a[3]), "r"(b0), "r"(b1));
}

// ----------------------------------------------------------------------------
__global__ void init_kernel() {
    int i = blockIdx.x * blockDim.x + threadIdx.x;   // 131072 threads
    unsigned short* hb = (unsigned short*)&d_hb[0][0][0];
    float* cb = &d_cbuf[0][0];
    if (i < 2 * 2 * Bv * Hv) hb[i] = 0;              // bf16 +0
    if (i < 2 * Bv * Hv)     cb[i] = 0.0f;
}

__global__ void embed_kernel(const int* __restrict__ X, const float* __restrict__ emb) {
    int row = blockIdx.x;
    int t = row >> 6, b = row & 63;
    int v = X[b * Sv + t];
    const float* src = emb + (size_t)v * Dv;
    __nv_bfloat16* dst = &d_Eb[(size_t)row * Dv];
    for (int k = threadIdx.x; k < Dv; k += 128) dst[k] = __float2bfloat16(src[k]);
}

// pack [Wih | Whh] -> bf16 combined K=1024 rows
__global__ void conv_lstm_w(const float* __restrict__ Wih, const float* __restrict__ Whh) {
    size_t i = (size_t)blockIdx.x * blockDim.x + threadIdx.x;   // 2*2048*1024
    int k = (int)(i & 1023);
    size_t lj = i >> 10;            // l*2048 + j
    int j = (int)(lj & 2047);
    int l = (int)(lj >> 11);
    float v = (k < 512) ? Wih[((size_t)l * 2048 + j) * 512 + k]
                        : Whh[((size_t)l * 2048 + j) * 512 + (k - 512)];
    (&d_Wc[0][0][0])[i] = __float2bfloat16(v);
}

// ----------------------------------------------------------------------------
// fp32 GEMM kept for the two small H x H products
// ----------------------------------------------------------------------------
__global__ __launch_bounds__(256) void gemm_nt(
    const float* __restrict__ A, int lda,
    const float* __restrict__ Bm, int ldb,
    const float* __restrict__ bias,
    float* __restrict__ C, int ldc,
    int M, int N, int K)
{
    __shared__ float As[16][128];
    __shared__ float Bs[16][128];
    const int bm = blockIdx.y * 128, bn = blockIdx.x * 128;
    const int tid = threadIdx.x;
    const int tm = (tid >> 4) << 3;
    const int tn = (tid & 15) << 3;

    float acc[8][8];
#pragma unroll
    for (int i = 0; i < 8; i++)
#pragma unroll
        for (int j = 0; j < 8; j++) acc[i][j] = 0.0f;

    for (int k0 = 0; k0 < K; k0 += 16) {
#pragma unroll
        for (int i = 0; i < 2; i++) {
            int idx = tid + i * 256;
            int r = idx >> 2;
            int k4 = (idx & 3) << 2;
            float4 v = make_float4(0.f, 0.f, 0.f, 0.f);
            if (bm + r < M) v = *(const float4*)(A + (size_t)(bm + r) * lda + k0 + k4);
            As[k4 + 0][r] = v.x; As[k4 + 1][r] = v.y; As[k4 + 2][r] = v.z; As[k4 + 3][r] = v.w;
        }
#pragma unroll
        for (int i = 0; i < 2; i++) {
            int idx = tid + i * 256;
            int r = idx >> 2;
            int k4 = (idx & 3) << 2;
            float4 v = make_float4(0.f, 0.f, 0.f, 0.f);
            if (bn + r < N) v = *(const float4*)(Bm + (size_t)(bn + r) * ldb + k0 + k4);
            Bs[k4 + 0][r] = v.x; Bs[k4 + 1][r] = v.y; Bs[k4 + 2][r] = v.z; Bs[k4 + 3][r] = v.w;
        }
        __syncthreads();
#pragma unroll
        for (int kk = 0; kk < 16; kk++) {
            float a[8], b[8];
            *(float4*)&a[0] = *(const float4*)&As[kk][tm];
            *(float4*)&a[4] = *(const float4*)&As[kk][tm + 4];
            *(float4*)&b[0] = *(const float4*)&Bs[kk][tn];
            *(float4*)&b[4] = *(const float4*)&Bs[kk][tn + 4];
#pragma unroll
            for (int i = 0; i < 8; i++)
#pragma unroll
                for (int j = 0; j < 8; j++) acc[i][j] += a[i] * b[j];
        }
        __syncthreads();
    }

#pragma unroll
    for (int i = 0; i < 8; i++) {
        int m = bm + tm + i;
        if (m >= M) continue;
#pragma unroll
        for (int j = 0; j < 8; j += 4) {
            int n = bn + tn + j;
            if (n + 3 < N) {
                float4 v;
                float b0 = bias ? bias[n + 0] : 0.f;
                float b1 = bias ? bias[n + 1] : 0.f;
                float b2 = bias ? bias[n + 2] : 0.f;
                float b3 = bias ? bias[n + 3] : 0.f;
                v.x = acc[i][j + 0] + b0;
                v.y = acc[i][j + 1] + b1;
                v.z = acc[i][j + 2] + b2;
                v.w = acc[i][j + 3] + b3;
                *(float4*)(C + (size_t)m * ldc + n) = v;
            }
        }
    }
}

// ----------------------------------------------------------------------------
// Persistent 2-layer LSTM with HMMA gates.
// Block bid owns 16 output cols (4 gates x 4 units); G[64x16] = In[64x1024].Wc^T.
// 8 warps = 4 m-tiles x 2 n-halves; warp tile 16x8; K-chunks of 64, double buffered.
// ----------------------------------------------------------------------------
struct LstmSmem {
    char sA[2][8192];       // 64 rows x 128B (bf16, sw128)
    char sW[2][2048];       // 16 rows x 128B
    float gb[64][17];
};

__global__ __launch_bounds__(256) void lstm_kernel(
    const float* __restrict__ bih, const float* __restrict__ bhh)
{
    __shared__ LstmSmem sm;
    const int bid = blockIdx.x, tid = threadIdx.x;
    const int wid = tid >> 5, lane = tid & 31;
    const int mtile = wid & 3, wn = wid >> 2;

    const uint32_t uA0 = smem_u32(sm.sA[0]), uA1 = smem_u32(sm.sA[1]);
    const uint32_t uW0 = smem_u32(sm.sW[0]), uW1 = smem_u32(sm.sW[1]);

    // pointwise-thread biases (b = tid>>2, i2 = tid&3), per layer per gate
    float bias[2][4];
#pragma unroll
    for (int l = 0; l < 2; l++)
#pragma unroll
        for (int g = 0; g < 4; g++) {
            int j = l * 2048 + g * 512 + bid * 4 + (tid & 3);
            bias[l][g] = bih[j] + bhh[j];
        }

    // precomputed ldmatrix offsets
    const uint32_t aoff = sw128((uint32_t)((mtile * 16 + (lane & 15)) * 128 + ((lane >> 4) << 4)));
    const uint32_t woff = sw128((uint32_t)(((((lane >> 4) << 3) + (lane & 7)) * 128) + (((lane >> 3) & 1) << 4)));

    for (int t = 0; t < Tv; t++) {
        const int p = t & 1;
        for (int l = 0; l < 2; l++) {
            // chunk loader
            auto load_chunk = [&](int kc, int buf) {
                const int koff = kc * 64;
                const __nv_bfloat16* abase;
                if (l == 0) abase = (koff < 512) ? (d_Eb + (size_t)t * Bv * 512 + koff)
                                                 : (&d_hb[0][p][0] + (koff - 512));
                else        abase = (koff < 512) ? (&d_hb[0][p ^ 1][0] + koff)
                                                 : (&d_hb[1][p][0] + (koff - 512));
                uint32_t ua = buf ? uA1 : uA0;
#pragma unroll
                for (int q = 0; q < 2; q++) {
                    int s = tid + q * 256;
                    int row = s >> 3, seg = s & 7;
                    cp_async16(ua + sw128((uint32_t)(row * 128 + seg * 16)),
                               (const char*)(abase + (size_t)row * 512) + seg * 16);
                }
                if (tid < 128) {
                    int r = tid >> 3, seg = tid & 7;
                    int gid = (r >> 2) * 512 + bid * 4 + (r & 3);
                    uint32_t uw = buf ? uW1 : uW0;
                    cp_async16(uw + sw128((uint32_t)(r * 128 + seg * 16)),
                               (const char*)(&d_Wc[l][gid][0] + koff) + seg * 16);
                }
                cp_commit();
            };

            load_chunk(0, 0);
            float c4[4] = {0.f, 0.f, 0.f, 0.f};

            for (int kc = 0; kc < 16; kc++) {
                if (kc + 1 < 16) {
                    load_chunk(kc + 1, (kc + 1) & 1);
                    asm volatile("cp.async.wait_group 1;" ::: "memory");
                } else {
                    asm volatile("cp.async.wait_group 0;" ::: "memory");
                }
                __syncthreads();
                const uint32_t ua = (kc & 1) ? uA1 : uA0;
                const uint32_t uw = (kc & 1) ? uW1 : uW0;
#pragma unroll
                for (int ks = 0; ks < 4; ks++) {
                    uint32_t af[4], bf[4];
                    ldmx4(af, ua + (aoff ^ (uint32_t)(ks * 32)));
                    ldmx4(bf, uw + (woff ^ (uint32_t)(ks * 32)));
                    mma_bf16(c4, af, bf[wn * 2], bf[wn * 2 + 1]);
                }
                __syncthreads();
            }

            // fragment -> gb
            {
                int r0 = mtile * 16 + (lane >> 2);
                int n0 = wn * 8 + (lane & 3) * 2;
                sm.gb[r0][n0] = c4[0];     sm.gb[r0][n0 + 1] = c4[1];
                sm.gb[r0 + 8][n0] = c4[2]; sm.gb[r0 + 8][n0 + 1] = c4[3];
            }
            __syncthreads();

            // pointwise gate update
            {
                int b = tid >> 2, i2 = tid & 3;
                float ig = sm.gb[b][0 + i2]  + bias[l][0];
                float fg = sm.gb[b][4 + i2]  + bias[l][1];
                float gg = sm.gb[b][8 + i2]  + bias[l][2];
                float og = sm.gb[b][12 + i2] + bias[l][3];
                int h2 = bid * 4 + i2;
                float cprev = d_cbuf[l][b * 512 + h2];
                float cn = sigm(fg) * cprev + sigm(ig) * tanhf(gg);
                float hn = sigm(og) * tanhf(cn);
                d_cbuf[l][b * 512 + h2] = cn;
                d_hb[l][p ^ 1][b * 512 + h2] = __float2bfloat16(hn);
                if (l == 1) d_cat[(size_t)(t * 64 + b) * 1024 + h2] = hn;
            }
            if (l == 0) grid_barrier();
            else        __syncthreads();
        }
    }
}

// ----------------------------------------------------------------------------
__global__ void scores_kernel(const float* __restrict__ vw) {
    __shared__ float sP[512];
    __shared__ float sv[512];
    int tb = blockIdx.x;
    int t = tb >> 6, b = tb & 63;
    int tid = threadIdx.x;
    for (int k = tid; k < 512; k += 256) { sP[k] = d_ptop[(size_t)tb * 512 + k]; sv[k] = vw[k]; }
    __syncthreads();
    int w = tid >> 5, lane = tid & 31;
    for (int e = w; e < Tv; e += 8) {
        const float* ep = &d_encproj[((size_t)b * Tv + e) * 512];
        float s = 0.f;
        for (int k = lane; k < 512; k += 32) s += tanhf(sP[k] + ep[k]) * sv[k];
#pragma unroll
        for (int o = 16; o; o >>= 1) s += __shfl_xor_sync(0xffffffffu, s, o);
        if (lane == 0) d_scores[((size_t)t * Tv + e) * 64 + b] = s;
    }
}

__global__ void att_kernel(const unsigned char* __restrict__ mask) {
    __shared__ float red[64];
    int te = blockIdx.x;
    int t = te / Tv, e = te - t * Tv;
    int tid = threadIdx.x;
    int mrow = (t + Tv - 1) % Tv;
    float val = (mask[mrow * Tv + e] != 0) ? -1.0e9f : d_scores[(size_t)te * 64 + tid];
    red[tid] = val; __syncthreads();
    for (int s = 32; s; s >>= 1) { if (tid < s) red[tid] = fmaxf(red[tid], red[tid + s]); __syncthreads(); }
    float mx = red[0]; __syncthreads();
    float ev = expf(val - mx);
    red[tid] = ev; __syncthreads();
    for (int s = 32; s; s >>= 1) { if (tid < s) red[tid] += red[tid + s]; __syncthreads(); }
    d_att[((size_t)t * 64 + tid) * Tv + e] = ev / red[0];
}

__global__ void weighted_kernel(const float* __restrict__ enc) {
    __shared__ float sa[64];
    int tb = blockIdx.x;
    int b = tb & 63;
    int tid = threadIdx.x;
    if (tid < Tv) sa[tid] = d_att[(size_t)tb * Tv + tid];
    __syncthreads();
    const float* eb = enc + (size_t)b * Tv * 512;
    float acc = 0.f;
    for (int e = 0; e < Tv; e++) acc += sa[e] * eb[e * 512 + tid];
    d_cat[(size_t)tb * 1024 + 512 + tid] = acc;
}

// ----------------------------------------------------------------------------
__global__ void conv_cat_kernel() {
    size_t i = (size_t)blockIdx.x * blockDim.x + threadIdx.x;
    size_t row = i >> 9;
    float2 v = make_float2(0.f, 0.f);
    if (row < (size_t)Tv * Bv) v = *((const float2*)d_cat + i);
    *((__nv_bfloat162*)d_catb + i) = __floats2bfloat162_rn(v.x, v.y);
}
__global__ void conv_w_kernel(const float* __restrict__ fcW) {
    size_t i = (size_t)blockIdx.x * blockDim.x + threadIdx.x;
    float2 v = *((const float2*)fcW + i);
    *((__nv_bfloat162*)d_fcWb + i) = __floats2bfloat162_rn(v.x, v.y);
}

// exact fp32 target logit per row
__global__ void tgt_kernel(const int* __restrict__ X, const float* __restrict__ fcW,
                           const float* __restrict__ fcb) {
    int r = blockIdx.x * 8 + (threadIdx.x >> 5);
    int lane = threadIdx.x & 31;
    if (r >= Tv * Bv) return;
    int t = r >> 6, b = r & 63;
    int tgt = X[b * Sv + t + 1];
    const float* a = d_cat + (size_t)r * 1024;
    const float* w = fcW + (size_t)tgt * 1024;
    float s = 0.f;
    for (int k = lane; k < 1024; k += 32) s += a[k] * w[k];
#pragma unroll
    for (int o = 16; o; o >>= 1) s += __shfl_xor_sync(0xffffffffu, s, o);
    if (lane == 0) d_ltgt[r] = s + fcb[tgt];
}

// ----------------------------------------------------------------------------
// HMMA bf16 GEMM with fused exp-sum epilogue (no logits materialization).
// ----------------------------------------------------------------------------
#define SA_OFF  0
#define SB_OFF  32768
#define SM_DYN  65536

__global__ __launch_bounds__(256, 2) void gemm_hmma(const float* __restrict__ fcb)
{
    extern __shared__ char smem[];
    const uint32_t sbase = smem_u32(smem);
    const int tid = threadIdx.x, wid = tid >> 5, lane = tid & 31;
    const int wm = wid & 3, wn = wid >> 2;
    const int m0 = blockIdx.x * GM;
    const int n0 = blockIdx.y * GN;

    float c[2][8][4];
#pragma unroll
    for (int mt = 0; mt < 2; mt++)
#pragma unroll
        for (int nt = 0; nt < 8; nt++)
#pragma unroll
            for (int k = 0; k < 4; k++) c[mt][nt][k] = 0.0f;

    const __nv_bfloat16* Ag = d_catb + (size_t)m0 * 1024;
    const __nv_bfloat16* Bg = d_fcWb + (size_t)n0 * 1024;

#pragma unroll
    for (int p = 0; p < 4; p++) {
        int i = tid + p * 256;
        int row = i >> 3, seg = i & 7;
        uint32_t off = sw128((uint32_t)(row * 128 + seg * 16));
        cp_async16(sbase + SA_OFF + off, (const char*)(Ag + (size_t)row * 1024) + seg * 16);
    }
#pragma unroll
    for (int p = 0; p < 4; p++) {
        int i = tid + p * 256;
        int row = i >> 3, seg = i & 7;
        uint32_t off = sw128((uint32_t)(row * 128 + seg * 16));
        cp_async16(sbase + SB_OFF + off, (const char*)(Bg + (size_t)row * 1024) + seg * 16);
    }
    cp_commit();

    for (int it = 0; it < NKC; it++) {
        if (it + 1 < NKC) {
            const int k0 = (it + 1) * GKC;
            const uint32_t bufo = ((it + 1) & 1) * 16384;
#pragma unroll
            for (int p = 0; p < 4; p++) {
                int i = tid + p * 256;
                int row = i >> 3, seg = i & 7;
                uint32_t off = sw128((uint32_t)(row * 128 + seg * 16));
                cp_async16(sbase + SA_OFF + bufo + off,
                           (const char*)(Ag + (size_t)row * 1024 + k0) + seg * 16);
            }
#pragma unroll
            for (int p = 0; p < 4; p++) {
                int i = tid + p * 256;
                int row = i >> 3, seg = i & 7;
                uint32_t off = sw128((uint32_t)(row * 128 + seg * 16));
                cp_async16(sbase + SB_OFF + bufo + off,
                           (const char*)(Bg + (size_t)row * 1024 + k0) + seg * 16);
            }
            cp_commit();
            asm volatile("cp.async.wait_group 1;" ::: "memory");
        } else {
            asm volatile("cp.async.wait_group 0;" ::: "memory");
        }
        __syncthreads();

        const uint32_t abase = sbase + SA_OFF + (it & 1) * 16384;
        const uint32_t bbase = sbase + SB_OFF + (it & 1) * 16384;
#pragma unroll
        for (int ks = 0; ks < 4; ks++) {
            uint32_t af[2][4];
#pragma unroll
            for (int mt = 0; mt < 2; mt++) {
                int arow = wm * 32 + mt * 16 + (lane & 15);
                int acol = ks * 32 + ((lane >> 4) << 4);
                ldmx4(af[mt], abase + sw128((uint32_t)(arow * 128 + acol)));
            }
            uint32_t bf[4][4];
#pragma unroll
            for (int j = 0; j < 4; j++) {
                int brow = wn * 64 + j * 16 + ((lane >> 4) << 3) + (lane & 7);
                int bcol = ks * 32 + (((lane >> 3) & 1) << 4);
                ldmx4(bf[j], bbase + sw128((uint32_t)(brow * 128 + bcol)));
            }
#pragma unroll
            for (int mt = 0; mt < 2; mt++)
#pragma unroll
                for (int nt = 0; nt < 8; nt++)
                    mma_bf16(c[mt][nt], af[mt], bf[nt >> 1][(nt & 1) * 2], bf[nt >> 1][(nt & 1) * 2 + 1]);
        }
        __syncthreads();
    }

    // ---- fused epilogue: per-row sum of exp(logit + bias) over this n-tile ----
    float* rowsum = (float*)smem;            // [128][2]
#pragma unroll
    for (int mt = 0; mt < 2; mt++) {
        float s0 = 0.f, s1 = 0.f;
#pragma unroll
        for (int nt = 0; nt < 8; nt++) {
            int col = n0 + wn * 64 + nt * 8 + (lane & 3) * 2;
            float b0 = fcb[col], b1 = fcb[col + 1];
            s0 += __expf(c[mt][nt][0] + b0) + __expf(c[mt][nt][1] + b1);
            s1 += __expf(c[mt][nt][2] + b0) + __expf(c[mt][nt][3] + b1);
        }
#pragma unroll
        for (int o = 1; o <= 2; o <<= 1) {
            s0 += __shfl_xor_sync(0xffffffffu, s0, o);
            s1 += __shfl_xor_sync(0xffffffffu, s1, o);
        }
        if ((lane & 3) == 0) {
            int r = wm * 32 + mt * 16 + (lane >> 2);
            rowsum[r * 2 + wn] = s0;
            rowsum[(r + 8) * 2 + wn] = s1;
        }
    }
    __syncthreads();
    if (tid < 128) {
        d_psum[(size_t)(m0 + tid) * 256 + blockIdx.y] = rowsum[tid * 2] + rowsum[tid * 2 + 1];
    }
}

// ----------------------------------------------------------------------------
// combine partial sums + target logit -> per-row nll
__global__ void loss_kernel(const int* __restrict__ X) {
    __shared__ float red[64];
    int r = blockIdx.x;
    int tid = threadIdx.x;           // 64
    float s = 0.f;
    for (int i = tid; i < NTILES; i += 64) s += d_psum[(size_t)r * 256 + i];
    red[tid] = s; __syncthreads();
    for (int k = 32; k; k >>= 1) { if (tid < k) red[tid] += red[tid + k]; __syncthreads(); }
    if (tid == 0) {
        int t = r >> 6, b = r & 63;
        int tgt = X[b * Sv + t + 1];
        float nll = logf(red[0]) - d_ltgt[r];
        bool valid = (tgt != 0);
        d_nll[r] = valid ? nll : 0.f;
        d_cnt[r] = valid ? 1.f : 0.f;
    }
}

__global__ void final_kernel(float* __restrict__ out) {
    __shared__ float red[64];
    int tid = threadIdx.x;
    float lt = 0.f;
    if (tid < Tv) {
        float s = 0.f, c = 0.f;
        for (int b = 0; b < 64; b++) { s += d_nll[tid * 64 + b]; c += d_cnt[tid * 64 + b]; }
        lt = s / c;
    }
    red[tid] = lt; __syncthreads();
    for (int s = 32; s; s >>= 1) { if (tid < s) red[tid] += red[tid + s]; __syncthreads(); }
    if (tid == 0) out[0] = red[0] / (float)Tv;
}

// ----------------------------------------------------------------------------
extern "C" void kernel_launch(void* const* d_in, const int* in_sizes, int n_in,
                              void* d_out, int out_size)
{
    const int*   X    = (const int*)d_in[0];
    const float* enc  = (const float*)d_in[1];
    const unsigned char* mask = (const unsigned char*)d_in[2];
    const float* emb  = (const float*)d_in[3];
    const float* Wih  = (const float*)d_in[4];
    const float* Whh  = (const float*)d_in[5];
    const float* bih  = (const float*)d_in[6];
    const float* bhh  = (const float*)d_in[7];
    const float* aWh  = (const float*)d_in[8];
    const float* aWe  = (const float*)d_in[9];
    const float* ab   = (const float*)d_in[10];
    const float* vw   = (const float*)d_in[11];
    const float* fcW  = (const float*)d_in[12];
    const float* fcb  = (const float*)d_in[13];
    float* out = (float*)d_out;

    float *p_encproj, *p_ptop, *p_cat;
    cudaGetSymbolAddress((void**)&p_encproj, d_encproj);
    cudaGetSymbolAddress((void**)&p_ptop,    d_ptop);
    cudaGetSymbolAddress((void**)&p_cat,     d_cat);

    cudaFuncSetAttribute(gemm_hmma, cudaFuncAttributeMaxDynamicSharedMemorySize, SM_DYN);

    init_kernel<<<256, 512>>>();
    embed_kernel<<<Tv * Bv, 128>>>(X, emb);
    conv_lstm_w<<<(2 * 2048 * 1024) / 256, 256>>>(Wih, Whh);
    gemm_nt<<<dim3(4, 32), 256>>>(enc, Hv, aWe, Hv, ab, p_encproj, Hv, Tv * Bv, Hv, Hv);
    lstm_kernel<<<NBL, 256>>>(bih, bhh);
    gemm_nt<<<dim3(4, 32), 256>>>(p_cat, 2 * Hv, aWh, Hv, nullptr, p_ptop, Hv, Tv * Bv, Hv, Hv);
    scores_kernel<<<Tv * Bv, 256>>>(vw);
    att_kernel<<<Tv * Tv, 64>>>(mask);
    weighted_kernel<<<Tv * Bv, 512>>>(enc);
    conv_w_kernel<<<(Vvoc * 1024 / 2) / 256, 256>>>(fcW);
    conv_cat_kernel<<<(MPAD * 1024 / 2) / 256, 256>>>();
    tgt_kernel<<<(Tv * Bv + 7) / 8, 256>>>(X, fcW, fcb);
    gemm_hmma<<<dim3(MPAD / GM, NTILES), 256, SM_DYN>>>(fcb);
    loss_kernel<<<Tv * Bv, 64>>>(X);
    final_kernel<<<1, 64>>>(out);
}